// round 2
// baseline (speedup 1.0000x reference)
#include <cuda_runtime.h>
#include <cstdint>
#include <cstddef>

// ---------------------------------------------------------------------------
// BufferAttend1d: B=8, Q=K=4096, DIM_IN=256, KEY_DIM=VAL_DIM=64
//   q = x @ Wk^T + bk ; k = buffer @ Wk^T + bk ; v = buffer @ Wv^T + bv
//   logits = q k^T / 8 ; masked -> -1024 ; probs = softmax ; read = probs @ v
// Output: probs (8*4096*4096 f32) then read (8*4096*64 f32), concatenated.
//
// TF32 mma.sync (RNA-rounded) everywhere. Two passes over K per q-tile:
//   Pass A: e = keep * exp2(l * log2e) (no max-subtract; logits provably
//           small, masked probs exactly 0), accumulate rowsum and O = e@V.
//   Pass B: recompute QK, write probs = e * (1/rowsum).
// ---------------------------------------------------------------------------

#define SEQ   4096
#define NB    8
#define DIN   256
#define HD    64
#define NROWS (NB * SEQ)                         // 32768
#define PROBS_ELEMS (8LL * 4096LL * 4096LL)

// scratch (allocation-free rule: __device__ globals)
__device__ float g_Q[NROWS * HD];
__device__ float g_K[NROWS * HD];
__device__ float g_V[NROWS * HD];
__device__ float g_keep[NROWS];
__device__ int   g_mask_fmt;

__device__ __forceinline__ uint32_t f2tf(float x) {
    uint32_t y;
    asm("cvt.rna.tf32.f32 %0, %1;" : "=r"(y) : "f"(x));
    return y;
}

__device__ __forceinline__ float fexp2(float x) {
    float y;
    asm("ex2.approx.f32 %0, %1;" : "=f"(y) : "f"(x));
    return y;
}

__device__ __forceinline__ void mma8(float* c, const uint32_t* a, const uint32_t* b) {
    asm volatile(
        "mma.sync.aligned.m16n8k8.row.col.f32.tf32.tf32.f32 "
        "{%0,%1,%2,%3}, {%4,%5,%6,%7}, {%8,%9}, {%0,%1,%2,%3};\n"
        : "+f"(c[0]), "+f"(c[1]), "+f"(c[2]), "+f"(c[3])
        : "r"(a[0]), "r"(a[1]), "r"(a[2]), "r"(a[3]), "r"(b[0]), "r"(b[1]));
}

__device__ __forceinline__ void zero_acc(float acc[2][4][4]) {
#pragma unroll
    for (int i = 0; i < 2; i++)
#pragma unroll
        for (int j = 0; j < 4; j++)
#pragma unroll
            for (int k = 0; k < 4; k++)
                acc[i][j][k] = 0.0f;
}

// ---------------------------------------------------------------------------
// Mask format detection + decode (bool8 vs int32 vs float32 is ambiguous)
// ---------------------------------------------------------------------------
__global__ void mask_detect_kernel(const uint32_t* __restrict__ mw) {
    __shared__ int iok_s, fok_s;
    if (threadIdx.x == 0) { iok_s = 1; fok_s = 1; }
    __syncthreads();
    int iok = 1, fok = 1;
    // first 8192 words = 32768 bytes: within bounds for every candidate dtype
    for (int i = threadIdx.x; i < NROWS / 4; i += blockDim.x) {
        uint32_t v = mw[i];
        if (v != 0u && v != 1u) iok = 0;
        if (v != 0u && v != 0x3F800000u) fok = 0;
    }
    if (!iok) atomicExch(&iok_s, 0);
    if (!fok) atomicExch(&fok_s, 0);
    __syncthreads();
    if (threadIdx.x == 0) g_mask_fmt = iok_s ? 1 : (fok_s ? 2 : 0);
}

__global__ void mask_decode_kernel(const void* __restrict__ mp) {
    int i = blockIdx.x * blockDim.x + threadIdx.x;
    if (i >= NROWS) return;
    int fmt = g_mask_fmt;
    int masked;
    if (fmt == 1)      masked = ((const int*)mp)[i] != 0;
    else if (fmt == 2) masked = ((const float*)mp)[i] != 0.0f;
    else               masked = ((const unsigned char*)mp)[i] != 0;
    g_keep[i] = masked ? 0.0f : 1.0f;   // mask True = masked out
}

// ---------------------------------------------------------------------------
// 128x64(out) += A(128xk64) @ B(64 rows x k64)^T   [K-major, stride 68]
// Warp layout: 8 warps = wm(0..3) x wn(0..1); each warp 32(M) x 32(N).
// ---------------------------------------------------------------------------
__device__ __forceinline__ void mma_block_128x64(
    const float* __restrict__ A, const float* __restrict__ Bm,
    float acc[2][4][4], int wm, int wn, int g, int t)
{
#pragma unroll
    for (int ks = 0; ks < 8; ks++) {
        const int k0 = ks * 8;
        uint32_t a[2][4], bb[4][2];
#pragma unroll
        for (int mi = 0; mi < 2; mi++) {
            const float* ap = A + (wm * 32 + mi * 16 + g) * 68 + k0 + t;
            a[mi][0] = f2tf(ap[0]);
            a[mi][1] = f2tf(ap[8 * 68]);
            a[mi][2] = f2tf(ap[4]);
            a[mi][3] = f2tf(ap[8 * 68 + 4]);
        }
#pragma unroll
        for (int ni = 0; ni < 4; ni++) {
            const float* bp = Bm + (wn * 32 + ni * 8 + g) * 68 + k0 + t;
            bb[ni][0] = f2tf(bp[0]);
            bb[ni][1] = f2tf(bp[4]);
        }
#pragma unroll
        for (int mi = 0; mi < 2; mi++)
#pragma unroll
            for (int ni = 0; ni < 4; ni++)
                mma8(acc[mi][ni], a[mi], bb[ni]);
    }
}

// O(128x64) += E(128 x k64) @ V(k64 x 64)   [V stored row=key, col=vd, stride 68]
__device__ __forceinline__ void pv_block(
    const float* __restrict__ E, const float* __restrict__ V,
    float acc[2][4][4], int wm, int wn, int g, int t)
{
#pragma unroll
    for (int ks = 0; ks < 8; ks++) {
        const int k0 = ks * 8;
        uint32_t a[2][4], bb[4][2];
#pragma unroll
        for (int mi = 0; mi < 2; mi++) {
            const float* ap = E + (wm * 32 + mi * 16 + g) * 68 + k0 + t;
            a[mi][0] = f2tf(ap[0]);
            a[mi][1] = f2tf(ap[8 * 68]);
            a[mi][2] = f2tf(ap[4]);
            a[mi][3] = f2tf(ap[8 * 68 + 4]);
        }
#pragma unroll
        for (int ni = 0; ni < 4; ni++) {
            const int n = wn * 32 + ni * 8 + g;
            bb[ni][0] = f2tf(V[(k0 + t) * 68 + n]);
            bb[ni][1] = f2tf(V[(k0 + t + 4) * 68 + n]);
        }
#pragma unroll
        for (int mi = 0; mi < 2; mi++)
#pragma unroll
            for (int ni = 0; ni < 4; ni++)
                mma8(acc[mi][ni], a[mi], bb[ni]);
    }
}

// ---------------------------------------------------------------------------
// Projection: blocks [0,256): x -> g_Q ;  blocks [256,512): buffer -> g_K,g_V
// ---------------------------------------------------------------------------
#define PROJ_SMEM_FLOATS (128 * 68 + 64 * 68)
#define PROJ_SMEM_BYTES  (PROJ_SMEM_FLOATS * 4)

__global__ __launch_bounds__(256) void proj_kernel(
    const float* __restrict__ x, const float* __restrict__ buf,
    const float* __restrict__ Wk, const float* __restrict__ bk,
    const float* __restrict__ Wv, const float* __restrict__ bv)
{
    extern __shared__ float sm[];
    float* As = sm;                // 128 x 68
    float* Ws = sm + 128 * 68;     // 64 x 68

    const int tid = threadIdx.x;
    const int lane = tid & 31, wid = tid >> 5;
    const int g = lane >> 2, t = lane & 3;
    const int wm = wid & 3, wn = wid >> 2;
    const bool isx = blockIdx.x < 256;
    const int row0 = (blockIdx.x & 255) * 128;
    const float* in = isx ? x : buf;
    const int nsweep = isx ? 1 : 2;

    for (int sw = 0; sw < nsweep; sw++) {
        const float* W    = (sw == 0) ? Wk : Wv;
        const float* bias = (sw == 0) ? bk : bv;
        float* out = isx ? g_Q : (sw == 0 ? g_K : g_V);

        float acc[2][4][4];
        zero_acc(acc);

        for (int kc = 0; kc < 4; kc++) {
            __syncthreads();
            for (int i = tid; i < 128 * 16; i += 256) {
                int r = i >> 4, c = (i & 15) * 4;
                float4 v = *(const float4*)&in[(size_t)(row0 + r) * DIN + kc * 64 + c];
                *(float4*)&As[r * 68 + c] = v;
            }
            for (int i = tid; i < 64 * 16; i += 256) {
                int r = i >> 4, c = (i & 15) * 4;
                float4 v = *(const float4*)&W[(size_t)r * DIN + kc * 64 + c];
                *(float4*)&Ws[r * 68 + c] = v;
            }
            __syncthreads();
            mma_block_128x64(As, Ws, acc, wm, wn, g, t);
        }

#pragma unroll
        for (int mi = 0; mi < 2; mi++) {
#pragma unroll
            for (int ni = 0; ni < 4; ni++) {
                int r = row0 + wm * 32 + mi * 16 + g;
                int col = wn * 32 + ni * 8 + t * 2;
                float b0v = __ldg(&bias[col]);
                float b1v = __ldg(&bias[col + 1]);
                out[(size_t)r * HD + col]           = acc[mi][ni][0] + b0v;
                out[(size_t)r * HD + col + 1]       = acc[mi][ni][1] + b1v;
                out[(size_t)(r + 8) * HD + col]     = acc[mi][ni][2] + b0v;
                out[(size_t)(r + 8) * HD + col + 1] = acc[mi][ni][3] + b1v;
            }
        }
    }
}

// ---------------------------------------------------------------------------
// Attention: one CTA per (b, q-tile of 128). Two passes over K.
// ---------------------------------------------------------------------------
#define KS_OFF (128 * 68)
#define VS_OFF (KS_OFF + 64 * 68)
#define ES_OFF (VS_OFF + 64 * 68)
#define KP_OFF (ES_OFF + 128 * 68)
#define RS_OFF (KP_OFF + 64)
#define IV_OFF (RS_OFF + 128)
#define ATTN_SMEM_FLOATS (IV_OFF + 128)
#define ATTN_SMEM_BYTES  (ATTN_SMEM_FLOATS * 4)

__global__ __launch_bounds__(256, 2) void attn_kernel(float* __restrict__ outp)
{
    extern __shared__ float sm[];
    float* Qs     = sm;             // 128 x 68 (pre-scaled by log2e/8)
    float* Ks     = sm + KS_OFF;    // 64 x 68
    float* Vs     = sm + VS_OFF;    // 64 x 68
    float* Es     = sm + ES_OFF;    // 128 x 68
    float* kp     = sm + KP_OFF;    // 64
    float* rowsum = sm + RS_OFF;    // 128
    float* invs   = sm + IV_OFF;    // 128

    const int tid = threadIdx.x;
    const int lane = tid & 31, wid = tid >> 5;
    const int g = lane >> 2, t = lane & 3;
    const int wm = wid & 3, wn = wid >> 2;
    const int b = blockIdx.x >> 5;
    const int q0 = (blockIdx.x & 31) * 128;
    const int kbase = b << 12;

    // stage Q pre-scaled by (1/8) * log2(e) so e = exp2(mma result)
    const float qscale = 0.125f * 1.4426950408889634f;
    for (int i = tid; i < 128 * 16; i += 256) {
        int r = i >> 4, c = (i & 15) * 4;
        float4 v = *(const float4*)&g_Q[(size_t)(kbase + q0 + r) * HD + c];
        v.x *= qscale; v.y *= qscale; v.z *= qscale; v.w *= qscale;
        *(float4*)&Qs[r * 68 + c] = v;
    }
    if (tid < 128) rowsum[tid] = 0.0f;
    __syncthreads();

    float o[2][4][4];
    zero_acc(o);

    // ------------------ Pass A: rowsum + O = e @ V ------------------
    for (int kt = 0; kt < 64; kt++) {
        const int kr0 = kbase + kt * 64;
        __syncthreads();
        for (int i = tid; i < 64 * 16; i += 256) {
            int r = i >> 4, c = (i & 15) * 4;
            size_t gi = (size_t)(kr0 + r) * HD + c;
            *(float4*)&Ks[r * 68 + c] = *(const float4*)&g_K[gi];
            *(float4*)&Vs[r * 68 + c] = *(const float4*)&g_V[gi];
        }
        if (tid < 64) kp[tid] = g_keep[kr0 + tid];
        __syncthreads();

        float lfr[2][4][4];
        zero_acc(lfr);
        mma_block_128x64(Qs, Ks, lfr, wm, wn, g, t);

        float rsum[2][2] = {{0.f, 0.f}, {0.f, 0.f}};
#pragma unroll
        for (int mi = 0; mi < 2; mi++) {
            const int r = wm * 32 + mi * 16 + g;
#pragma unroll
            for (int ni = 0; ni < 4; ni++) {
                const int col = wn * 32 + ni * 8 + t * 2;
                const float k0v = kp[col], k1v = kp[col + 1];
                float e00 = k0v * fexp2(lfr[mi][ni][0]);
                float e01 = k1v * fexp2(lfr[mi][ni][1]);
                float e10 = k0v * fexp2(lfr[mi][ni][2]);
                float e11 = k1v * fexp2(lfr[mi][ni][3]);
                Es[r * 68 + col] = e00;       Es[r * 68 + col + 1] = e01;
                Es[(r + 8) * 68 + col] = e10; Es[(r + 8) * 68 + col + 1] = e11;
                rsum[mi][0] += e00 + e01;
                rsum[mi][1] += e10 + e11;
            }
        }
#pragma unroll
        for (int mi = 0; mi < 2; mi++) {
#pragma unroll
            for (int h = 0; h < 2; h++) {
                float v = rsum[mi][h];
                v += __shfl_xor_sync(0xffffffffu, v, 1);
                v += __shfl_xor_sync(0xffffffffu, v, 2);
                if (t == 0) atomicAdd(&rowsum[wm * 32 + mi * 16 + h * 8 + g], v);
            }
        }
        __syncthreads();

        pv_block(Es, Vs, o, wm, wn, g, t);
    }

    __syncthreads();
    if (tid < 128) invs[tid] = 1.0f / rowsum[tid];
    __syncthreads();

    // write `read` output
    {
        float* rout = outp + PROBS_ELEMS;
#pragma unroll
        for (int mi = 0; mi < 2; mi++) {
            const int r = wm * 32 + mi * 16 + g;
            const float i0 = invs[r], i1 = invs[r + 8];
#pragma unroll
            for (int ni = 0; ni < 4; ni++) {
                const int col = wn * 32 + ni * 8 + t * 2;
                size_t o0 = (size_t)(kbase + q0 + r) * HD + col;
                size_t o1 = (size_t)(kbase + q0 + r + 8) * HD + col;
                rout[o0]     = o[mi][ni][0] * i0;
                rout[o0 + 1] = o[mi][ni][1] * i0;
                rout[o1]     = o[mi][ni][2] * i1;
                rout[o1 + 1] = o[mi][ni][3] * i1;
            }
        }
    }

    // ------------------ Pass B: recompute QK, write probs -----------
    for (int kt = 0; kt < 64; kt++) {
        const int kr0 = kbase + kt * 64;
        __syncthreads();
        for (int i = tid; i < 64 * 16; i += 256) {
            int r = i >> 4, c = (i & 15) * 4;
            *(float4*)&Ks[r * 68 + c] = *(const float4*)&g_K[(size_t)(kr0 + r) * HD + c];
        }
        if (tid < 64) kp[tid] = g_keep[kr0 + tid];
        __syncthreads();

        float lfr[2][4][4];
        zero_acc(lfr);
        mma_block_128x64(Qs, Ks, lfr, wm, wn, g, t);

#pragma unroll
        for (int mi = 0; mi < 2; mi++) {
            const int r = wm * 32 + mi * 16 + g;
            const float i0 = invs[r], i1 = invs[r + 8];
#pragma unroll
            for (int ni = 0; ni < 4; ni++) {
                const int col = wn * 32 + ni * 8 + t * 2;
                const float k0v = kp[col] * i0, k1v = kp[col + 1] * i0;
                const float k2v = kp[col] * i1, k3v = kp[col + 1] * i1;
                float2 p0, p1;
                p0.x = k0v * fexp2(lfr[mi][ni][0]);
                p0.y = k1v * fexp2(lfr[mi][ni][1]);
                p1.x = k2v * fexp2(lfr[mi][ni][2]);
                p1.y = k3v * fexp2(lfr[mi][ni][3]);
                size_t base0 = ((size_t)(kbase + q0 + r)) * SEQ + kt * 64 + col;
                size_t base1 = ((size_t)(kbase + q0 + r + 8)) * SEQ + kt * 64 + col;
                *(float2*)&outp[base0] = p0;
                *(float2*)&outp[base1] = p1;
            }
        }
    }
}

// ---------------------------------------------------------------------------
extern "C" void kernel_launch(void* const* d_in, const int* in_sizes, int n_in,
                              void* d_out, int out_size) {
    const float* x   = (const float*)d_in[0];
    const float* buf = (const float*)d_in[1];
    const void*  msk = d_in[2];
    const float* Wk  = (const float*)d_in[3];
    const float* bk  = (const float*)d_in[4];
    const float* Wv  = (const float*)d_in[5];
    const float* bv  = (const float*)d_in[6];
    float* outp = (float*)d_out;

    cudaFuncSetAttribute(proj_kernel, cudaFuncAttributeMaxDynamicSharedMemorySize,
                         PROJ_SMEM_BYTES);
    cudaFuncSetAttribute(attn_kernel, cudaFuncAttributeMaxDynamicSharedMemorySize,
                         ATTN_SMEM_BYTES);

    proj_kernel<<<512, 256, PROJ_SMEM_BYTES>>>(x, buf, Wk, bk, Wv, bv);
    mask_detect_kernel<<<1, 256>>>((const uint32_t*)msk);
    mask_decode_kernel<<<NROWS / 256, 256>>>(msk);
    attn_kernel<<<256, 256, ATTN_SMEM_BYTES>>>(outp);
}